// round 11
// baseline (speedup 1.0000x reference)
#include <cuda_runtime.h>
#include <cuda_bf16.h>
#include <cstdint>
#include <cstddef>

#define NN 1024
#define EE 128
#define A_STRIDE 136
#define SMEM_BYTES 73216
#define GEMM_GRID 304

__device__ float         g_cb[NN * EE];     // c_term + pc_b, [j][k]
__device__ float         g_q[NN];           // wf@a1 + a_b
__device__ float         g_w2[EE];          // W@a2
__device__ __nv_bfloat16 g_Bt[EE * EE];     // Bt[n][k] = pc_Wp[k][n]
__device__ float         g_logT[NN * NN];   // logits transposed [j][i]

__device__ __forceinline__ float lrelu(float x) { return 0.6f * x + 0.4f * fabsf(x); }

// ---- prep 1: per-row wf, cb[j], q[j] ----
__global__ void GNAH_prep_cb_q(const float* __restrict__ embs, const float* __restrict__ W,
                               const float* __restrict__ pc_W, const float* __restrict__ pc_b,
                               const float* __restrict__ a_W, const float* __restrict__ a_b) {
    __shared__ float er[EE], wf_s[EE], red[EE];
    int j = blockIdx.x, t = threadIdx.x;
    er[t] = embs[j * EE + t];
    __syncthreads();
    float a = 0.f;
    #pragma unroll 8
    for (int e = 0; e < EE; e++) a += er[e] * W[e * EE + t];
    wf_s[t] = a;
    __syncthreads();
    float c = pc_b[t];
    #pragma unroll 8
    for (int e = 0; e < EE; e++) c += wf_s[e] * pc_W[e * EE + t];
    g_cb[j * EE + t] = c;
    red[t] = wf_s[t] * a_W[t];
    __syncthreads();
    for (int s = 64; s > 0; s >>= 1) { if (t < s) red[t] += red[t + s]; __syncthreads(); }
    if (t == 0) g_q[j] = red[0] + a_b[0];
}

// ---- prep 2: Bt (bf16) and w2 ----
__global__ void GNAH_prep_w2_Bt(const float* __restrict__ W, const float* __restrict__ pc_W,
                                const float* __restrict__ a_W) {
    __shared__ float red[EE];
    int n = blockIdx.x, t = threadIdx.x;
    g_Bt[n * EE + t] = __float2bfloat16(pc_W[(EE + t) * EE + n]);
    red[t] = W[n * EE + t] * a_W[EE + t];
    __syncthreads();
    for (int s = 64; s > 0; s >>= 1) { if (t < s) red[t] += red[t + s]; __syncthreads(); }
    if (t == 0) g_w2[n] = red[0];
}

__device__ __forceinline__ void mma_bf16(float& d0, float& d1, float& d2, float& d3,
                                         unsigned a0, unsigned a1, unsigned a2, unsigned a3,
                                         unsigned b0, unsigned b1) {
    asm volatile("mma.sync.aligned.m16n8k16.row.col.f32.bf16.bf16.f32 "
                 "{%0,%1,%2,%3}, {%4,%5,%6,%7}, {%8,%9}, {%0,%1,%2,%3};"
                 : "+f"(d0), "+f"(d1), "+f"(d2), "+f"(d3)
                 : "r"(a0), "r"(a1), "r"(a2), "r"(a3), "r"(b0), "r"(b1));
}

// ---- main: fused GEMM (128x128x128 per tile, fixed j) + lrelu-dot epilogue ----
__global__ __launch_bounds__(256, 2) void GNAH_gemm_kernel(const float* __restrict__ pde) {
    extern __shared__ unsigned char sm_raw[];
    __nv_bfloat16* A_s = reinterpret_cast<__nv_bfloat16*>(sm_raw);
    __nv_bfloat16* B_s = reinterpret_cast<__nv_bfloat16*>(sm_raw + 34816);
    float* cbv  = reinterpret_cast<float*>(sm_raw + 69632);
    float* qv   = cbv + 128;
    float* w2v  = qv + 128;
    float* part = w2v + 128;   // 4 x 128

    const int t = threadIdx.x;
    const int lane = t & 31, warp = t >> 5;
    const int wm = warp >> 2, wn = warp & 3;
    const int m0 = wm * 64, n0 = wn * 32;

    for (int idx = t; idx < EE * EE; idx += 256)
        B_s[(idx >> 7) * A_STRIDE + (idx & 127)] = g_Bt[idx];
    if (t < 128) w2v[t] = g_w2[t];

    unsigned a_sm = (unsigned)__cvta_generic_to_shared(A_s);
    unsigned b_sm = (unsigned)__cvta_generic_to_shared(B_s);
    int mA = lane >> 3;
    int rA = (mA & 1) * 8 + (lane & 7);
    int cA = (mA >> 1) * 8;
    int lB = lane & 15;
    int rB = lB & 7;
    int cB = (lB >> 3) * 8;
    unsigned aAddr[4], bAddr[4];
    #pragma unroll
    for (int fm = 0; fm < 4; fm++)
        aAddr[fm] = a_sm + (unsigned)(((m0 + 16 * fm + rA) * A_STRIDE + cA) * 2);
    #pragma unroll
    for (int fn = 0; fn < 4; fn++)
        bAddr[fn] = b_sm + (unsigned)(((n0 + 8 * fn + rB) * A_STRIDE + cB) * 2);

    const int gq = lane >> 2, cq = lane & 3;
    const float4* pde4 = reinterpret_cast<const float4*>(pde);

    for (int tt = blockIdx.x; tt < 8192; tt += gridDim.x) {
        const int jj = tt >> 3;
        const int i0 = (tt & 7) << 7;

        __syncthreads();
        if (t < 128) { cbv[t] = g_cb[jj * EE + t]; qv[t] = g_q[i0 + t]; }

        size_t base = ((size_t)i0 * 1024 + (size_t)jj) * 32;   // float4 units
        #pragma unroll
        for (int it = 0; it < 16; it++) {
            int lin = it * 256 + t;
            int row = lin >> 5;
            int c4  = lin & 31;
            float4 v = __ldcs(pde4 + base + (size_t)row * 32768 + c4);
            __nv_bfloat162 lo = __floats2bfloat162_rn(v.x, v.y);
            __nv_bfloat162 hi = __floats2bfloat162_rn(v.z, v.w);
            uint2 pk;
            pk.x = *reinterpret_cast<unsigned*>(&lo);
            pk.y = *reinterpret_cast<unsigned*>(&hi);
            *reinterpret_cast<uint2*>(&A_s[row * A_STRIDE + c4 * 4]) = pk;
        }
        __syncthreads();

        float acc[4][4][4];
        #pragma unroll
        for (int fm = 0; fm < 4; fm++)
            #pragma unroll
            for (int fn = 0; fn < 4; fn++)
                #pragma unroll
                for (int v = 0; v < 4; v++) acc[fm][fn][v] = 0.f;

        #pragma unroll
        for (int kk = 0; kk < 8; kk++) {
            unsigned af[4][4], bfr[4][2];
            #pragma unroll
            for (int fm = 0; fm < 4; fm++)
                asm volatile("ldmatrix.sync.aligned.m8n8.x4.shared.b16 {%0,%1,%2,%3}, [%4];"
                             : "=r"(af[fm][0]), "=r"(af[fm][1]), "=r"(af[fm][2]), "=r"(af[fm][3])
                             : "r"(aAddr[fm] + kk * 32));
            #pragma unroll
            for (int fn = 0; fn < 4; fn++)
                asm volatile("ldmatrix.sync.aligned.m8n8.x2.shared.b16 {%0,%1}, [%2];"
                             : "=r"(bfr[fn][0]), "=r"(bfr[fn][1])
                             : "r"(bAddr[fn] + kk * 32));
            #pragma unroll
            for (int fm = 0; fm < 4; fm++)
                #pragma unroll
                for (int fn = 0; fn < 4; fn++)
                    mma_bf16(acc[fm][fn][0], acc[fm][fn][1], acc[fm][fn][2], acc[fm][fn][3],
                             af[fm][0], af[fm][1], af[fm][2], af[fm][3],
                             bfr[fn][0], bfr[fn][1]);
        }

        float w2r[8], cbr[8];
        #pragma unroll
        for (int fn = 0; fn < 4; fn++) {
            int col = n0 + 8 * fn + 2 * cq;
            w2r[2 * fn]     = w2v[col];
            w2r[2 * fn + 1] = w2v[col + 1];
            cbr[2 * fn]     = cbv[col];
            cbr[2 * fn + 1] = cbv[col + 1];
        }
        #pragma unroll
        for (int fm = 0; fm < 4; fm++) {
            float r0 = 0.f, r1 = 0.f;
            #pragma unroll
            for (int fn = 0; fn < 4; fn++) {
                r0 += lrelu(acc[fm][fn][0] + cbr[2 * fn])     * w2r[2 * fn];
                r0 += lrelu(acc[fm][fn][1] + cbr[2 * fn + 1]) * w2r[2 * fn + 1];
                r1 += lrelu(acc[fm][fn][2] + cbr[2 * fn])     * w2r[2 * fn];
                r1 += lrelu(acc[fm][fn][3] + cbr[2 * fn + 1]) * w2r[2 * fn + 1];
            }
            r0 += __shfl_xor_sync(0xffffffffu, r0, 1);
            r0 += __shfl_xor_sync(0xffffffffu, r0, 2);
            r1 += __shfl_xor_sync(0xffffffffu, r1, 1);
            r1 += __shfl_xor_sync(0xffffffffu, r1, 2);
            if (cq == 0) {
                part[wn * 128 + m0 + 16 * fm + gq]     = r0;
                part[wn * 128 + m0 + 16 * fm + gq + 8] = r1;
            }
        }
        __syncthreads();
        if (t < 128) {
            float s = part[t] + part[128 + t] + part[256 + t] + part[384 + t];
            g_logT[(size_t)jj * 1024 + i0 + t] = lrelu(qv[t] + s);
        }
    }
}

// ---- softmax (bounded logits -> no max-sub) + attn@embs + concat ----
__global__ __launch_bounds__(256) void GNAH_attn_kernel(const float* __restrict__ embs,
                                                        const int* __restrict__ adj,
                                                        float* __restrict__ out) {
    __shared__ float4 emb_s[64 * 32];
    __shared__ float  w_s[64 * 8];
    __shared__ float  spart[256];
    __shared__ float  S_s[8];

    const int t = threadIdx.x;
    const int i0 = blockIdx.x * 8;
    const int il = t & 7;
    const int e4 = t >> 3;
    const int wj = t >> 3;

    const float4* embs4 = reinterpret_cast<const float4*>(embs);
    float4 acc = make_float4(0.f, 0.f, 0.f, 0.f);
    float esum = 0.f;

    for (int j0 = 0; j0 < 1024; j0 += 64) {
        #pragma unroll
        for (int r = 0; r < 8; r++) {
            int lin = r * 256 + t;
            emb_s[lin] = embs4[(size_t)(j0 + (lin >> 5)) * 32 + (lin & 31)];
        }
        #pragma unroll
        for (int h = 0; h < 2; h++) {
            int jc = wj + h * 32;
            int j  = j0 + jc;
            float w = 0.f;
            if (adj[(i0 + il) * 1024 + j] == 1)
                w = __expf(g_logT[(size_t)j * 1024 + i0 + il]);
            w_s[jc * 8 + il] = w;
            esum += w;
        }
        __syncthreads();
        #pragma unroll 8
        for (int j = 0; j < 64; j++) {
            float w = w_s[j * 8 + il];
            float4 e = emb_s[j * 32 + e4];
            acc.x += w * e.x; acc.y += w * e.y; acc.z += w * e.z; acc.w += w * e.w;
        }
        __syncthreads();
    }
    spart[t] = esum;
    __syncthreads();
    if (t < 8) {
        float s = 0.f;
        for (int k = t; k < 256; k += 8) s += spart[k];
        S_s[t] = s;
    }
    __syncthreads();
    float inv = 1.0f / S_s[il];
    acc.x *= inv; acc.y *= inv; acc.z *= inv; acc.w *= inv;

    float4* out4 = reinterpret_cast<float4*>(out);
    out4[(size_t)(i0 + il) * 64 + 32 + e4] = acc;           // nbc half
    int r = t >> 5, c = t & 31;
    out4[(size_t)(i0 + r) * 64 + c] = embs4[(size_t)(i0 + r) * 32 + c];  // embs half
}

extern "C" void kernel_launch(void* const* d_in, const int* in_sizes, int n_in,
                              void* d_out, int out_size) {
    const float* embs = (const float*)d_in[0];
    const int*   adj  = (const int*)d_in[1];
    const float* pde  = (const float*)d_in[2];
    const float* W    = (const float*)d_in[3];
    const float* pc_W = (const float*)d_in[4];
    const float* pc_b = (const float*)d_in[5];
    const float* a_W  = (const float*)d_in[6];
    const float* a_b  = (const float*)d_in[7];
    float* out = (float*)d_out;

    cudaFuncSetAttribute(GNAH_gemm_kernel,
                         cudaFuncAttributeMaxDynamicSharedMemorySize, SMEM_BYTES);

    GNAH_prep_cb_q<<<NN, EE>>>(embs, W, pc_W, pc_b, a_W, a_b);
    GNAH_prep_w2_Bt<<<EE, EE>>>(W, pc_W, a_W);
    GNAH_gemm_kernel<<<GEMM_GRID, 256, SMEM_BYTES>>>(pde);
    GNAH_attn_kernel<<<NN / 8, 256>>>(embs, adj, out);
}

// round 13
// speedup vs baseline: 1.0663x; 1.0663x over previous
#include <cuda_runtime.h>
#include <cuda_bf16.h>
#include <cstdint>
#include <cstddef>

#define NN 1024
#define EE 128
#define A_STRIDE 136
#define A_BUF_BYTES 34816            // 128 x 136 bf16
#define SMEM_BYTES 109056            // 2*A + B + 4608 extras
#define GEMM_GRID 304

__device__ float         g_cb[NN * EE];     // c_term + pc_b, [j][k]
__device__ float         g_q[NN];           // wf@a1 + a_b
__device__ float         g_w2[EE];          // W@a2
__device__ __nv_bfloat16 g_Bt[EE * EE];     // Bt[n][k] = pc_Wp[k][n]
__device__ float         g_logT[NN * NN];   // logits transposed [j][i]
__device__ float         g_esum[8 * NN];    // [bj][i] partial exp sums
__device__ float4        g_nbcp[8 * NN * 32]; // [bj][i][e4] partial weighted sums

__device__ __forceinline__ float lrelu(float x) { return 0.6f * x + 0.4f * fabsf(x); }

// ---- prep 1: per-row wf, cb[j], q[j] ----
__global__ void GNAH_prep_cb_q(const float* __restrict__ embs, const float* __restrict__ W,
                               const float* __restrict__ pc_W, const float* __restrict__ pc_b,
                               const float* __restrict__ a_W, const float* __restrict__ a_b) {
    __shared__ float er[EE], wf_s[EE], red[EE];
    int j = blockIdx.x, t = threadIdx.x;
    er[t] = embs[j * EE + t];
    __syncthreads();
    float a = 0.f;
    #pragma unroll 8
    for (int e = 0; e < EE; e++) a += er[e] * W[e * EE + t];
    wf_s[t] = a;
    __syncthreads();
    float c = pc_b[t];
    #pragma unroll 8
    for (int e = 0; e < EE; e++) c += wf_s[e] * pc_W[e * EE + t];
    g_cb[j * EE + t] = c;
    red[t] = wf_s[t] * a_W[t];
    __syncthreads();
    for (int s = 64; s > 0; s >>= 1) { if (t < s) red[t] += red[t + s]; __syncthreads(); }
    if (t == 0) g_q[j] = red[0] + a_b[0];
}

// ---- prep 2: Bt (bf16) and w2 ----
__global__ void GNAH_prep_w2_Bt(const float* __restrict__ W, const float* __restrict__ pc_W,
                                const float* __restrict__ a_W) {
    __shared__ float red[EE];
    int n = blockIdx.x, t = threadIdx.x;
    g_Bt[n * EE + t] = __float2bfloat16(pc_W[(EE + t) * EE + n]);
    red[t] = W[n * EE + t] * a_W[EE + t];
    __syncthreads();
    for (int s = 64; s > 0; s >>= 1) { if (t < s) red[t] += red[t + s]; __syncthreads(); }
    if (t == 0) g_w2[n] = red[0];
}

__device__ __forceinline__ void mma_bf16(float& d0, float& d1, float& d2, float& d3,
                                         unsigned a0, unsigned a1, unsigned a2, unsigned a3,
                                         unsigned b0, unsigned b1) {
    asm volatile("mma.sync.aligned.m16n8k16.row.col.f32.bf16.bf16.f32 "
                 "{%0,%1,%2,%3}, {%4,%5,%6,%7}, {%8,%9}, {%0,%1,%2,%3};"
                 : "+f"(d0), "+f"(d1), "+f"(d2), "+f"(d3)
                 : "r"(a0), "r"(a1), "r"(a2), "r"(a3), "r"(b0), "r"(b1));
}

// ---- main: fused GEMM (128x128x128 per tile, fixed j) + lrelu-dot epilogue,
// ----       double-buffered A with loads interleaved into the MMA k-loop.
__global__ __launch_bounds__(256, 2) void GNAH_gemm_kernel(const float* __restrict__ pde) {
    extern __shared__ unsigned char sm_raw[];
    __nv_bfloat16* A_s = reinterpret_cast<__nv_bfloat16*>(sm_raw);            // 2 buffers
    __nv_bfloat16* B_s = reinterpret_cast<__nv_bfloat16*>(sm_raw + 2 * A_BUF_BYTES);
    float* fx   = reinterpret_cast<float*>(sm_raw + 2 * A_BUF_BYTES + A_BUF_BYTES);
    float* cbv  = fx;          // [2][128]
    float* qv   = fx + 256;    // [2][128]
    float* w2v  = fx + 512;    // [128]
    float* part = fx + 640;    // [4][128]

    const int t = threadIdx.x;
    const int lane = t & 31, warp = t >> 5;
    const int wm = warp >> 2, wn = warp & 3;
    const int m0 = wm * 64, n0 = wn * 32;
    const int tr = t >> 5;     // row sub-index for tile loads
    const int c4 = t & 31;     // float4 column for tile loads

    for (int idx = t; idx < EE * EE; idx += 256)
        B_s[(idx >> 7) * A_STRIDE + (idx & 127)] = g_Bt[idx];
    if (t < 128) w2v[t] = g_w2[t];

    unsigned a_sm = (unsigned)__cvta_generic_to_shared(A_s);
    unsigned b_sm = (unsigned)__cvta_generic_to_shared(B_s);
    int mA = lane >> 3;
    int rA = (mA & 1) * 8 + (lane & 7);
    int cA = (mA >> 1) * 8;
    int lB = lane & 15;
    int rB = lB & 7;
    int cB = (lB >> 3) * 8;
    unsigned aAddr[4], bAddr[4];
    #pragma unroll
    for (int fm = 0; fm < 4; fm++)
        aAddr[fm] = a_sm + (unsigned)(((m0 + 16 * fm + rA) * A_STRIDE + cA) * 2);
    #pragma unroll
    for (int fn = 0; fn < 4; fn++)
        bAddr[fn] = b_sm + (unsigned)(((n0 + 8 * fn + rB) * A_STRIDE + cB) * 2);

    const int gq = lane >> 2, cq = lane & 3;
    const float4* pde4 = reinterpret_cast<const float4*>(pde);

    // ---- prologue: load tile 0 into buffer 0 ----
    {
        int tt = blockIdx.x;
        int jj = tt >> 3, i0 = (tt & 7) << 7;
        if (t < 128) { cbv[t] = g_cb[jj * EE + t]; qv[t] = g_q[i0 + t]; }
        size_t base = ((size_t)i0 * 1024 + (size_t)jj) * 32;
        #pragma unroll
        for (int it = 0; it < 16; it++) {
            int row = it * 8 + tr;
            float4 v = __ldcs(pde4 + base + (size_t)row * 32768 + c4);
            __nv_bfloat162 lo = __floats2bfloat162_rn(v.x, v.y);
            __nv_bfloat162 hi = __floats2bfloat162_rn(v.z, v.w);
            uint2 pk;
            pk.x = *reinterpret_cast<unsigned*>(&lo);
            pk.y = *reinterpret_cast<unsigned*>(&hi);
            *reinterpret_cast<uint2*>(&A_s[row * A_STRIDE + c4 * 4]) = pk;
        }
    }
    __syncthreads();

    int buf = 0;
    for (int tt = blockIdx.x; tt < 8192; tt += gridDim.x) {
        const int nt = tt + gridDim.x;
        const bool hn = nt < 8192;
        const int nbuf = buf ^ 1;
        __nv_bfloat16* An = A_s + nbuf * (A_BUF_BYTES / 2);
        size_t nbase = 0;
        if (hn) {
            int njj = nt >> 3, ni0 = (nt & 7) << 7;
            nbase = ((size_t)ni0 * 1024 + (size_t)njj) * 32;
            if (t < 128) { cbv[nbuf * 128 + t] = g_cb[njj * EE + t]; qv[nbuf * 128 + t] = g_q[ni0 + t]; }
        }

        unsigned aA[4];
        #pragma unroll
        for (int fm = 0; fm < 4; fm++) aA[fm] = aAddr[fm] + buf * A_BUF_BYTES;

        float4 pf[4];
        auto issue = [&](int g) {
            #pragma unroll
            for (int r = 0; r < 4; r++) {
                int row = g * 32 + r * 8 + tr;
                pf[r] = __ldcs(pde4 + nbase + (size_t)row * 32768 + c4);
            }
        };
        auto commit = [&](int g) {
            #pragma unroll
            for (int r = 0; r < 4; r++) {
                int row = g * 32 + r * 8 + tr;
                __nv_bfloat162 lo = __floats2bfloat162_rn(pf[r].x, pf[r].y);
                __nv_bfloat162 hi = __floats2bfloat162_rn(pf[r].z, pf[r].w);
                uint2 pk;
                pk.x = *reinterpret_cast<unsigned*>(&lo);
                pk.y = *reinterpret_cast<unsigned*>(&hi);
                *reinterpret_cast<uint2*>(&An[row * A_STRIDE + c4 * 4]) = pk;
            }
        };

        if (hn) issue(0);

        float acc[4][4][4];
        #pragma unroll
        for (int fm = 0; fm < 4; fm++)
            #pragma unroll
            for (int fn = 0; fn < 4; fn++)
                #pragma unroll
                for (int v = 0; v < 4; v++) acc[fm][fn][v] = 0.f;

        #pragma unroll
        for (int kk = 0; kk < 8; kk++) {
            unsigned af[4][4], bfr[4][2];
            #pragma unroll
            for (int fm = 0; fm < 4; fm++)
                asm volatile("ldmatrix.sync.aligned.m8n8.x4.shared.b16 {%0,%1,%2,%3}, [%4];"
                             : "=r"(af[fm][0]), "=r"(af[fm][1]), "=r"(af[fm][2]), "=r"(af[fm][3])
                             : "r"(aA[fm] + kk * 32));
            #pragma unroll
            for (int fn = 0; fn < 4; fn++)
                asm volatile("ldmatrix.sync.aligned.m8n8.x2.shared.b16 {%0,%1}, [%2];"
                             : "=r"(bfr[fn][0]), "=r"(bfr[fn][1])
                             : "r"(bAddr[fn] + kk * 32));
            #pragma unroll
            for (int fm = 0; fm < 4; fm++)
                #pragma unroll
                for (int fn = 0; fn < 4; fn++)
                    mma_bf16(acc[fm][fn][0], acc[fm][fn][1], acc[fm][fn][2], acc[fm][fn][3],
                             af[fm][0], af[fm][1], af[fm][2], af[fm][3],
                             bfr[fn][0], bfr[fn][1]);
            if (hn) {
                if (kk == 1) { commit(0); issue(1); }
                else if (kk == 3) { commit(1); issue(2); }
                else if (kk == 5) { commit(2); issue(3); }
                else if (kk == 7) { commit(3); }
            }
        }

        float w2r[8], cbr[8];
        #pragma unroll
        for (int fn = 0; fn < 4; fn++) {
            int col = n0 + 8 * fn + 2 * cq;
            w2r[2 * fn]     = w2v[col];
            w2r[2 * fn + 1] = w2v[col + 1];
            cbr[2 * fn]     = cbv[buf * 128 + col];
            cbr[2 * fn + 1] = cbv[buf * 128 + col + 1];
        }
        #pragma unroll
        for (int fm = 0; fm < 4; fm++) {
            float r0 = 0.f, r1 = 0.f;
            #pragma unroll
            for (int fn = 0; fn < 4; fn++) {
                r0 += lrelu(acc[fm][fn][0] + cbr[2 * fn])     * w2r[2 * fn];
                r0 += lrelu(acc[fm][fn][1] + cbr[2 * fn + 1]) * w2r[2 * fn + 1];
                r1 += lrelu(acc[fm][fn][2] + cbr[2 * fn])     * w2r[2 * fn];
                r1 += lrelu(acc[fm][fn][3] + cbr[2 * fn + 1]) * w2r[2 * fn + 1];
            }
            r0 += __shfl_xor_sync(0xffffffffu, r0, 1);
            r0 += __shfl_xor_sync(0xffffffffu, r0, 2);
            r1 += __shfl_xor_sync(0xffffffffu, r1, 1);
            r1 += __shfl_xor_sync(0xffffffffu, r1, 2);
            if (cq == 0) {
                part[wn * 128 + m0 + 16 * fm + gq]     = r0;
                part[wn * 128 + m0 + 16 * fm + gq + 8] = r1;
            }
        }
        __syncthreads();
        if (t < 128) {
            const int jj = tt >> 3, i0 = (tt & 7) << 7;
            float s = part[t] + part[128 + t] + part[256 + t] + part[384 + t];
            g_logT[(size_t)jj * 1024 + i0 + t] = lrelu(qv[buf * 128 + t] + s);
        }
        __syncthreads();   // part free + next A buffer visible
        buf ^= 1;
    }
}

// ---- attn pass 1: per (i-chunk, j-chunk) partial softmax-weighted sums ----
// grid = 1024: bi = blockIdx.x & 127 (8 i-rows), bj = blockIdx.x >> 7 (128 j-rows)
#define WS 9   // padded stride for [jl][il] smem
__global__ __launch_bounds__(256) void GNAH_attn1(const float* __restrict__ embs,
                                                  const int* __restrict__ adj) {
    __shared__ float lt_s[128 * WS];
    __shared__ float w_s[128 * WS];

    const int t = threadIdx.x;
    const int bi = blockIdx.x & 127, bj = blockIdx.x >> 7;
    const int i0 = bi * 8, j0 = bj * 128;

    // pass A: logT chunk -> smem (coalesced on i)
    #pragma unroll
    for (int it = 0; it < 4; it++) {
        int idx = it * 256 + t;
        int jl = idx >> 3, il = idx & 7;
        lt_s[jl * WS + il] = g_logT[(size_t)(j0 + jl) * 1024 + i0 + il];
    }
    __syncthreads();

    // pass B: mask + exp + partial esum (coalesced on j)
    {
        const int il = t >> 5;
        float epart = 0.f;
        #pragma unroll
        for (int s = 0; s < 4; s++) {
            int jl = s * 32 + (t & 31);
            float w = 0.f;
            if (adj[(size_t)(i0 + il) * 1024 + j0 + jl] == 1)
                w = __expf(lt_s[jl * WS + il]);
            w_s[jl * WS + il] = w;
            epart += w;
        }
        #pragma unroll
        for (int o = 16; o > 0; o >>= 1) epart += __shfl_xor_sync(0xffffffffu, epart, o);
        if ((t & 31) == 0) g_esum[bj * NN + i0 + il] = epart;
    }
    __syncthreads();

    // pass C: partial weighted emb sum; thread owns (il, e4)
    {
        const int il = t & 7, e4 = t >> 3;
        const float4* embs4 = reinterpret_cast<const float4*>(embs);
        float4 acc = make_float4(0.f, 0.f, 0.f, 0.f);
        #pragma unroll 8
        for (int jl = 0; jl < 128; jl++) {
            float w = w_s[jl * WS + il];
            float4 e = embs4[(size_t)(j0 + jl) * 32 + e4];
            acc.x += w * e.x; acc.y += w * e.y; acc.z += w * e.z; acc.w += w * e.w;
        }
        g_nbcp[((size_t)bj * NN + i0 + il) * 32 + e4] = acc;
    }
}

// ---- attn pass 2: reduce 8 partials, normalize, write both output halves ----
__global__ __launch_bounds__(256) void GNAH_attn2(const float* __restrict__ embs,
                                                  float* __restrict__ out) {
    const int t = threadIdx.x;
    const int i = blockIdx.x * 8 + (t >> 5);
    const int c = t & 31;
    float es = 0.f;
    #pragma unroll
    for (int bj = 0; bj < 8; bj++) es += g_esum[bj * NN + i];
    float4 a = make_float4(0.f, 0.f, 0.f, 0.f);
    #pragma unroll
    for (int bj = 0; bj < 8; bj++) {
        float4 p = g_nbcp[((size_t)bj * NN + i) * 32 + c];
        a.x += p.x; a.y += p.y; a.z += p.z; a.w += p.w;
    }
    float inv = 1.0f / es;
    a.x *= inv; a.y *= inv; a.z *= inv; a.w *= inv;
    const float4* embs4 = reinterpret_cast<const float4*>(embs);
    float4* out4 = reinterpret_cast<float4*>(out);
    out4[(size_t)i * 64 + 32 + c] = a;                   // nbc half
    out4[(size_t)i * 64 + c] = embs4[(size_t)i * 32 + c]; // embs half
}

extern "C" void kernel_launch(void* const* d_in, const int* in_sizes, int n_in,
                              void* d_out, int out_size) {
    const float* embs = (const float*)d_in[0];
    const int*   adj  = (const int*)d_in[1];
    const float* pde  = (const float*)d_in[2];
    const float* W    = (const float*)d_in[3];
    const float* pc_W = (const float*)d_in[4];
    const float* pc_b = (const float*)d_in[5];
    const float* a_W  = (const float*)d_in[6];
    const float* a_b  = (const float*)d_in[7];
    float* out = (float*)d_out;

    cudaFuncSetAttribute(GNAH_gemm_kernel,
                         cudaFuncAttributeMaxDynamicSharedMemorySize, SMEM_BYTES);

    GNAH_prep_cb_q<<<NN, EE>>>(embs, W, pc_W, pc_b, a_W, a_b);
    GNAH_prep_w2_Bt<<<EE, EE>>>(W, pc_W, a_W);
    GNAH_gemm_kernel<<<GEMM_GRID, 256, SMEM_BYTES>>>(pde);
    GNAH_attn1<<<1024, 256>>>(embs, adj);
    GNAH_attn2<<<NN / 8, 256>>>(embs, out);
}